// round 16
// baseline (speedup 1.0000x reference)
#include <cuda_runtime.h>
#include <cuda_fp16.h>
#include <cstdint>

#define NB 4
#define NS 2048
#define ND 1024
#define NH 16
#define DKH 64
#define MROWS (NB*NS)   // 8192
#define KX2 2048        // activation rows: 2 fp16 planes [hi | lo]

// ---------------- scratch (__device__ globals; no allocation) ----------------
__device__ __half g_xs[(size_t)MROWS * KX2];     // x split    [hi|lo] fp16
__device__ __half g_as[(size_t)MROWS * KX2];     // attn split [hi|lo] fp16
__device__ __half g_wqkv[(size_t)3 * ND * ND];   // Wq|Wk|Wv fp16 (1 plane)
__device__ __half g_wo[(size_t)ND * ND];         // Wo fp16 (1 plane)
__device__ __half g_q[(size_t)NB*NH*2*NS*DKH];   // Q: [bh][plane2][S][64]
__device__ __half g_k[(size_t)NB*NH*NS*DKH];     // K: [bh][S][64] (1 plane)
__device__ __half g_v[(size_t)NB*NH*NS*DKH];     // V: [bh][S][64] (1 plane)

// ---------------- helpers ----------------
__device__ __forceinline__ uint32_t smem_u32(const void* p) {
    uint32_t a;
    asm("{ .reg .u64 t; cvta.to.shared.u64 t, %1; cvt.u32.u64 %0, t; }" : "=r"(a) : "l"(p));
    return a;
}
__device__ __forceinline__ void ldsm4(uint32_t* r, uint32_t addr) {
    asm volatile("ldmatrix.sync.aligned.m8n8.x4.shared.b16 {%0,%1,%2,%3}, [%4];"
                 : "=r"(r[0]), "=r"(r[1]), "=r"(r[2]), "=r"(r[3]) : "r"(addr));
}
__device__ __forceinline__ void ldsm4t(uint32_t* r, uint32_t addr) {
    asm volatile("ldmatrix.sync.aligned.m8n8.x4.trans.shared.b16 {%0,%1,%2,%3}, [%4];"
                 : "=r"(r[0]), "=r"(r[1]), "=r"(r[2]), "=r"(r[3]) : "r"(addr));
}
// fp16 MMA, non-volatile (pure register op; lets ptxas interleave)
__device__ __forceinline__ void mma16816(float* c, const uint32_t* a, uint32_t b0, uint32_t b1) {
    asm("mma.sync.aligned.m16n8k16.row.col.f32.f16.f16.f32 "
        "{%0,%1,%2,%3}, {%4,%5,%6,%7}, {%8,%9}, {%0,%1,%2,%3};"
        : "+f"(c[0]), "+f"(c[1]), "+f"(c[2]), "+f"(c[3])
        : "r"(a[0]), "r"(a[1]), "r"(a[2]), "r"(a[3]), "r"(b0), "r"(b1));
}
__device__ __forceinline__ void cpasync16(uint32_t dst, const void* src) {
    asm volatile("cp.async.cg.shared.global [%0], [%1], 16;" :: "r"(dst), "l"(src));
}
__device__ __forceinline__ void cp_commit() {
    asm volatile("cp.async.commit_group;" ::: "memory");
}
__device__ __forceinline__ uint32_t packhf(float a, float b) {
    __half2 h = __floats2half2_rn(a, b);
    return *(uint32_t*)&h;
}
__device__ __forceinline__ uint32_t packhlo(float a, float b, uint32_t hbits) {
    __half2 h = *(__half2*)&hbits;
    return packhf(a - __low2float(h), b - __high2float(h));
}
__device__ __forceinline__ float ex2(float x) {
    float r; asm("ex2.approx.ftz.f32 %0, %1;" : "=f"(r) : "f"(x)); return r;
}

// log2(e) folded into Q so attention uses raw ex2
#define QSCALE (0.125f * 1.4426950408889634f)

__device__ __forceinline__ uint32_t swz128(uint32_t off) {
    return off ^ ((off >> 3) & 0x70);
}

// ---------------- fused fp32 -> fp16 conversion (one launch) ----------------
// Blocks [0, 16384): x -> 2-plane split.  [16384, 16384+4*2048): weights.
__global__ void split_all(const float* __restrict__ x,
                          const float* __restrict__ Wq, const float* __restrict__ Wk,
                          const float* __restrict__ Wv, const float* __restrict__ Wo,
                          __half* __restrict__ xs,
                          __half* __restrict__ wqkv, __half* __restrict__ wo)
{
    int blk = blockIdx.x;
    if (blk < 16384) {
        int i = blk * 256 + threadIdx.x;        // 0 .. 8192*512-1
        int r  = i >> 9;
        int cp = i & 511;
        float2 v = *(const float2*)(x + (size_t)r * ND + cp * 2);
        __half2 hh = __floats2half2_rn(v.x, v.y);
        __half2 ll = __floats2half2_rn(v.x - __low2float(hh), v.y - __high2float(hh));
        __half2* d2 = (__half2*)(xs + (size_t)r * KX2) + cp;
        d2[0]   = hh;
        d2[512] = ll;
    } else {
        int wb = blk - 16384;                   // 0 .. 4*2048-1
        int which = wb >> 11;                   // 2048 blocks per weight
        const float* src = (which == 0) ? Wq : (which == 1) ? Wk
                         : (which == 2) ? Wv : Wo;
        __half* dst = (which == 3) ? wo : wqkv + (size_t)which * ND * ND;
        int i = (wb & 2047) * 256 + threadIdx.x;  // 0 .. 1024*512-1
        int r  = i >> 9;
        int cp = i & 511;
        float2 v = *(const float2*)(src + (size_t)r * ND + cp * 2);
        ((__half2*)(dst + (size_t)r * ND))[cp] = __floats2half2_rn(v.x, v.y);
    }
}

// ---------------- HMMA fp16 NT GEMM: C = Ah*W^T + Al*W^T (frozen R13) -------
static constexpr int GEMM_NT   = 1024 / 64;   // 16 stages
static constexpr int STAGE_B   = 3 * 16384;   // 49152
static constexpr int GEMM_SMEM = 2 * STAGE_B; // 98304

__device__ __forceinline__ void gemm_cp(const __half* __restrict__ A,
                                        const __half* __restrict__ Bw,
                                        int m0, int n0, int k0,
                                        uint32_t sbuf, int tid)
{
    #pragma unroll
    for (int i = 0; i < 12; i++) {
        int c = tid + i * 256;            // 0..3071 16B chunks
        int tile = c >> 10;               // 0:Ah 1:Al 2:W
        int cc = c & 1023;
        int r = cc >> 3, col16 = cc & 7;
        const __half* src = (tile < 2)
            ? A  + (size_t)(m0 + r) * KX2 + tile * 1024 + k0 + col16 * 8
            : Bw + (size_t)(n0 + r) * ND + k0 + col16 * 8;
        uint32_t off = (uint32_t)(r * 128 + col16 * 16);
        cpasync16(sbuf + tile * 16384u + swz128(off), src);
    }
}

template<int OMODE>   // 0: fp32 out [M,ND]; 1: merged QKV -> head layouts
__global__ void __launch_bounds__(256, 2)
gemm_mma(const __half* __restrict__ A, const __half* __restrict__ Bw,
         float* __restrict__ outF,
         __half* __restrict__ qp, __half* __restrict__ kp, __half* __restrict__ vp)
{
    extern __shared__ __align__(1024) char smem[];
    const int tid  = threadIdx.x;
    const int lane = tid & 31;
    const int wid  = tid >> 5;
    const int warp_m = wid & 1;    // 2 x 64 rows
    const int warp_n = wid >> 1;   // 4 x 32 cols
    const int m0 = blockIdx.y * 128;
    const int n0 = blockIdx.x * 128;

    const uint32_t sbase = smem_u32(smem);
    const int qrow = lane & 15;
    const int qcol = lane >> 4;

    float acc[4][4][4];
    #pragma unroll
    for (int a = 0; a < 4; a++)
        #pragma unroll
        for (int b = 0; b < 4; b++)
            #pragma unroll
            for (int c = 0; c < 4; c++) acc[a][b][c] = 0.f;

    gemm_cp(A, Bw, m0, n0, 0, sbase, tid); cp_commit();

    #pragma unroll 1
    for (int t = 0; t < GEMM_NT; t++) {
        asm volatile("cp.async.wait_group 0;" ::: "memory");
        __syncthreads();
        if (t + 1 < GEMM_NT) {
            gemm_cp(A, Bw, m0, n0, (t + 1) * 64,
                    sbase + (uint32_t)((t + 1) & 1) * STAGE_B, tid);
            cp_commit();
        }

        const uint32_t sAh = sbase + (uint32_t)(t & 1) * STAGE_B;
        const uint32_t sAl = sAh + 16384u;
        const uint32_t sB  = sAh + 32768u;

        #pragma unroll
        for (int ks = 0; ks < 4; ks++) {
            uint32_t ah[4][4], al[4][4];
            #pragma unroll
            for (int mi = 0; mi < 4; mi++) {
                uint32_t off = (uint32_t)((warp_m * 64 + mi * 16 + qrow) * 128
                                          + (ks * 2 + qcol) * 16);
                off = swz128(off);
                ldsm4(ah[mi], sAh + off);
                ldsm4(al[mi], sAl + off);
            }
            #pragma unroll
            for (int nj = 0; nj < 2; nj++) {
                uint32_t bh[4];
                uint32_t off = (uint32_t)((warp_n * 32 + nj * 16 + qrow) * 128
                                          + (ks * 2 + qcol) * 16);
                ldsm4(bh, sB + swz128(off));
                #pragma unroll
                for (int mi = 0; mi < 4; mi++)
                    #pragma unroll
                    for (int c2 = 0; c2 < 2; c2++) {
                        float* cc = acc[mi][nj * 2 + c2];
                        mma16816(cc, ah[mi], bh[c2], bh[2 + c2]);
                        mma16816(cc, al[mi], bh[c2], bh[2 + c2]);
                    }
            }
        }
    }

    const int tr = lane >> 2;
    const int tc = (lane & 3) * 2;
    const int which = n0 >> 10;                 // 0:Q 1:K 2:V (OMODE 1)
    const float scale = (OMODE == 1 && which == 0) ? QSCALE : 1.f;
    const int ncol0 = n0 & 1023;

    #pragma unroll
    for (int mi = 0; mi < 4; mi++) {
        #pragma unroll
        for (int ni = 0; ni < 4; ni++) {
            const int row = m0 + warp_m * 64 + mi * 16 + tr;
            const int col = (OMODE ? ncol0 : n0) + warp_n * 32 + ni * 8 + tc;
            float* cc = acc[mi][ni];
            #pragma unroll
            for (int half = 0; half < 2; half++) {
                const int r = row + half * 8;
                float2 val = half ? make_float2(cc[2], cc[3]) : make_float2(cc[0], cc[1]);
                if (OMODE == 0) {
                    *(float2*)(outF + (size_t)r * ND + col) = val;
                } else {
                    val.x *= scale; val.y *= scale;
                    const int b = r >> 11, s = r & (NS - 1);
                    const int h = col >> 6, ch = col & 63;
                    if (which == 0) {   // Q: 2 fp16 planes
                        __half2 hi = __floats2half2_rn(val.x, val.y);
                        __half2 lo = __floats2half2_rn(val.x - __low2float(hi),
                                                       val.y - __high2float(hi));
                        __half* base = qp + (((size_t)(b * NH + h) * 2) * NS + s) * 64 + ch;
                        *(__half2*)base           = hi;
                        *(__half2*)(base + NS*64) = lo;
                    } else {            // K/V: single fp16 plane
                        __half* dst = ((which == 1) ? kp : vp)
                            + ((size_t)(b * NH + h) * NS + s) * 64 + ch;
                        *(__half2*)dst = __floats2half2_rn(val.x, val.y);
                    }
                }
            }
        }
    }
}

// ---------------------------------------------------------------------------
// HMMA fp16 causal flash attention — R13 best shape (64-row CTAs, 3 CTA/SM,
// 3-buffer KV ring, wait_group 1 deep prefetch). Grid: x=bh, y=qt (big first).
// ---------------------------------------------------------------------------
static constexpr int ATTN_SMEM = 16384 + 3 * 16384;  // 65536

__global__ void __launch_bounds__(128, 3)
fattn(const __half* __restrict__ Qg, const __half* __restrict__ Kg,
      const __half* __restrict__ Vg, __half* __restrict__ As)
{
    extern __shared__ __align__(1024) char sm[];
    const uint32_t sb = smem_u32(sm);
    const int bh  = blockIdx.x;
    const int qt  = (int)gridDim.y - 1 - (int)blockIdx.y;  // big tiles first
    const int tid = threadIdx.x, lane = tid & 31, w = tid >> 5;

    const __half* Qbh = Qg + (size_t)bh * 2 * NS * 64;
    const __half* Kbh = Kg + (size_t)bh * NS * 64;
    const __half* Vbh = Vg + (size_t)bh * NS * 64;

    // Q tile: 2 planes x 64 x 64 fp16 = 16KB, SW128 swizzle (128B rows)
    #pragma unroll
    for (int i = 0; i < 8; i++) {
        int c = tid + i * 128;             // 0..1023 16B chunks
        int p = c >> 9, r = (c >> 3) & 63, col16 = c & 7;
        uint4 v = *(const uint4*)(Qbh + (size_t)p * NS * 64
                                  + (size_t)(qt * 64 + r) * 64 + col16 * 8);
        uint32_t off = (uint32_t)(r * 128 + col16 * 16);
        *(uint4*)(sm + p * 8192 + swz128(off)) = v;
    }

    const int nkt = qt + 1;

    auto load_kv = [&](int kt, int buf) {
        const int kv0 = kt * 64;
        #pragma unroll
        for (int i = 0; i < 8; i++) {
            int c = tid + i * 128;         // 0..1023
            int p = c >> 9;                // 0:K 1:V
            int r = (c >> 3) & 63, col16 = c & 7;
            const __half* src = (p == 0 ? Kbh : Vbh)
                + (size_t)(kv0 + r) * 64 + col16 * 8;
            uint32_t off = (uint32_t)(r * 128 + col16 * 16);
            cpasync16(sb + 16384 + buf * 16384 + p * 8192 + swz128(off), src);
        }
        cp_commit();
    };

    load_kv(0, 0);
    if (nkt > 1) load_kv(1, 1);

    // hoisted Q-frag addresses (kt-invariant)
    uint32_t qaddr[4];
    #pragma unroll
    for (int ks = 0; ks < 4; ks++) {
        uint32_t off = (uint32_t)((w * 16 + (lane & 15)) * 128
                                  + (ks * 2 + (lane >> 4)) * 16);
        qaddr[ks] = sb + swz128(off);
    }

    float m[2], l[2];
    m[0] = m[1] = -1e30f;
    l[0] = l[1] = 0.f;

    float o[8][4];
    #pragma unroll
    for (int b = 0; b < 8; b++)
        #pragma unroll
        for (int c = 0; c < 4; c++) o[b][c] = 0.f;

    const int qw0 = qt * 64 + w * 16;

    int buf_c = 0;
    for (int kt = 0; kt < nkt; kt++) {
        if (kt + 1 < nkt) {
            asm volatile("cp.async.wait_group 1;" ::: "memory");
        } else {
            asm volatile("cp.async.wait_group 0;" ::: "memory");
        }
        __syncthreads();   // stage kt visible; all warps done with buf(kt-1)
        if (kt + 2 < nkt) {
            int bi = buf_c + 2; if (bi >= 3) bi -= 3;
            load_kv(kt + 2, bi);     // overlaps compute(kt) and wait(kt+1)
        }

        const uint32_t sK = sb + 16384 + (uint32_t)buf_c * 16384u;
        const uint32_t sV = sK + 8192u;

        float s_[8][4];
        #pragma unroll
        for (int b = 0; b < 8; b++)
            #pragma unroll
            for (int c = 0; c < 4; c++) s_[b][c] = 0.f;

        // ---- S = (Qh + Ql) * K16 ----
        #pragma unroll
        for (int ks = 0; ks < 4; ks++) {
            uint32_t ah[4], al[4], bb[4][4];
            ldsm4(ah, qaddr[ks]);            // Q hi
            ldsm4(al, qaddr[ks] + 8192u);    // Q lo
            #pragma unroll
            for (int nj = 0; nj < 4; nj++) {
                uint32_t off = (uint32_t)((nj * 16 + (lane & 15)) * 128
                                          + (ks * 2 + (lane >> 4)) * 16);
                ldsm4(bb[nj], sK + swz128(off));
            }
            #pragma unroll
            for (int ni = 0; ni < 8; ni++)
                mma16816(s_[ni], ah, bb[ni >> 1][ni & 1], bb[ni >> 1][2 + (ni & 1)]);
            #pragma unroll
            for (int ni = 0; ni < 8; ni++)
                mma16816(s_[ni], al, bb[ni >> 1][ni & 1], bb[ni >> 1][2 + (ni & 1)]);
        }

        // ---- causal mask (only when the tile crosses this warp's rows) ----
        if (kt * 64 + 63 > qw0) {
            #pragma unroll
            for (int ni = 0; ni < 8; ni++)
                #pragma unroll
                for (int c = 0; c < 4; c++) {
                    int qr = qw0 + ((c >> 1) << 3) + (lane >> 2);
                    int kc = kt * 64 + ni * 8 + ((lane & 3) << 1) + (c & 1);
                    if (kc > qr) s_[ni][c] = -1e30f;
                }
        }

        // ---- online softmax in log2 domain ----
        #pragma unroll
        for (int rh = 0; rh < 2; rh++) {
            float mx = -1e30f;
            #pragma unroll
            for (int ni = 0; ni < 8; ni++)
                mx = fmaxf(mx, fmaxf(s_[ni][rh*2], s_[ni][rh*2+1]));
            mx = fmaxf(mx, __shfl_xor_sync(0xffffffffu, mx, 1));
            mx = fmaxf(mx, __shfl_xor_sync(0xffffffffu, mx, 2));
            float mn = fmaxf(m[rh], mx);
            float sc = ex2(m[rh] - mn);
            m[rh] = mn;
            float sum = 0.f;
            #pragma unroll
            for (int ni = 0; ni < 8; ni++) {
                float p0 = ex2(s_[ni][rh*2]   - mn);
                float p1 = ex2(s_[ni][rh*2+1] - mn);
                s_[ni][rh*2] = p0; s_[ni][rh*2+1] = p1;
                sum += p0 + p1;
            }
            sum += __shfl_xor_sync(0xffffffffu, sum, 1);
            sum += __shfl_xor_sync(0xffffffffu, sum, 2);
            l[rh] = l[rh] * sc + sum;
            #pragma unroll
            for (int ni = 0; ni < 8; ni++) {
                o[ni][rh*2]   *= sc;
                o[ni][rh*2+1] *= sc;
            }
        }

        // ---- O += (Ph + Pl) * V16 ----
        #pragma unroll
        for (int ks = 0; ks < 4; ks++) {
            uint32_t ah[4], al[4], bv[4][4];
            const float* t0 = s_[2*ks];
            const float* t1 = s_[2*ks+1];
            ah[0] = packhf(t0[0], t0[1]);
            ah[1] = packhf(t0[2], t0[3]);
            ah[2] = packhf(t1[0], t1[1]);
            ah[3] = packhf(t1[2], t1[3]);
            al[0] = packhlo(t0[0], t0[1], ah[0]);
            al[1] = packhlo(t0[2], t0[3], ah[1]);
            al[2] = packhlo(t1[0], t1[1], ah[2]);
            al[3] = packhlo(t1[2], t1[3], ah[3]);
            #pragma unroll
            for (int nj = 0; nj < 4; nj++) {
                uint32_t off = (uint32_t)((ks * 16 + (lane & 15)) * 128
                                          + (nj * 2 + (lane >> 4)) * 16);
                ldsm4t(bv[nj], sV + swz128(off));
            }
            #pragma unroll
            for (int nd = 0; nd < 8; nd++) {
                uint32_t b0 = bv[nd >> 1][(nd & 1) * 2];
                uint32_t b1 = bv[nd >> 1][(nd & 1) * 2 + 1];
                mma16816(o[nd], ah, b0, b1);
                mma16816(o[nd], al, b0, b1);
            }
        }

        buf_c = (buf_c == 2) ? 0 : buf_c + 1;
    }

    // epilogue: O/l -> 2-plane fp16 rows [hi | lo] of Wo GEMM's A operand
    const int b = bh >> 4, h = bh & 15;
    #pragma unroll
    for (int rh = 0; rh < 2; rh++) {
        float invl = 1.f / l[rh];
        int row = qw0 + rh * 8 + (lane >> 2);
        __half* rbase = As + (size_t)(b * NS + row) * KX2 + h * 64;
        #pragma unroll
        for (int ni = 0; ni < 8; ni++) {
            float vx = o[ni][rh*2] * invl;
            float vy = o[ni][rh*2+1] * invl;
            __half2 hi = __floats2half2_rn(vx, vy);
            __half2 lo = __floats2half2_rn(vx - __low2float(hi),
                                           vy - __high2float(hi));
            __half* dst = rbase + ni * 8 + ((lane & 3) << 1);
            *(__half2*)dst          = hi;
            *(__half2*)(dst + 1024) = lo;
        }
    }
}

// ---------------------------------------------------------------------------
extern "C" void kernel_launch(void* const* d_in, const int* in_sizes, int n_in,
                              void* d_out, int out_size)
{
    const float* x  = (const float*)d_in[0];
    const float* Wq = (const float*)d_in[1];
    const float* Wk = (const float*)d_in[2];
    const float* Wv = (const float*)d_in[3];
    const float* Wo = (const float*)d_in[4];
    float* out = (float*)d_out;

    __half *xs, *as, *wqkv, *wo, *q, *k, *v;
    cudaGetSymbolAddress((void**)&xs,   g_xs);
    cudaGetSymbolAddress((void**)&as,   g_as);
    cudaGetSymbolAddress((void**)&wqkv, g_wqkv);
    cudaGetSymbolAddress((void**)&wo,   g_wo);
    cudaGetSymbolAddress((void**)&q,    g_q);
    cudaGetSymbolAddress((void**)&k,    g_k);
    cudaGetSymbolAddress((void**)&v,    g_v);

    cudaFuncSetAttribute(gemm_mma<0>, cudaFuncAttributeMaxDynamicSharedMemorySize, GEMM_SMEM);
    cudaFuncSetAttribute(gemm_mma<1>, cudaFuncAttributeMaxDynamicSharedMemorySize, GEMM_SMEM);
    cudaFuncSetAttribute(fattn, cudaFuncAttributeMaxDynamicSharedMemorySize, ATTN_SMEM);

    // fused conversion: x split + 4 weight planes in one launch
    split_all<<<16384 + 4 * 2048, 256>>>(x, Wq, Wk, Wv, Wo, xs, wqkv, wo);

    // fused QKV projection: N = 3072
    gemm_mma<1><<<dim3(3 * ND / 128, MROWS / 128), 256, GEMM_SMEM>>>(
        xs, wqkv, nullptr, q, k, v);

    fattn<<<dim3(NB * NH, NS / 64), 128, ATTN_SMEM>>>(q, k, v, as);

    gemm_mma<0><<<dim3(ND / 128, MROWS / 128), 256, GEMM_SMEM>>>(
        as, wo, out, nullptr, nullptr, nullptr);
}

// round 17
// speedup vs baseline: 1.5252x; 1.5252x over previous
#include <cuda_runtime.h>
#include <cuda_fp16.h>
#include <cstdint>

#define NB 4
#define NS 2048
#define ND 1024
#define NH 16
#define DKH 64
#define MROWS (NB*NS)   // 8192
#define KX2 2048        // activation rows: 2 fp16 planes [hi | lo]

// ---------------- scratch (__device__ globals; no allocation) ----------------
__device__ __half g_xs[(size_t)MROWS * KX2];     // x split    [hi|lo] fp16
__device__ __half g_as[(size_t)MROWS * KX2];     // attn split [hi|lo] fp16
__device__ __half g_wqkv[(size_t)3 * ND * ND];   // Wq|Wk|Wv fp16 (1 plane)
__device__ __half g_wo[(size_t)ND * ND];         // Wo fp16 (1 plane)
__device__ __half g_q[(size_t)NB*NH*2*NS*DKH];   // Q: [bh][plane2][S][64]
__device__ __half g_k[(size_t)NB*NH*NS*DKH];     // K: [bh][S][64] (1 plane)
__device__ __half g_v[(size_t)NB*NH*NS*DKH];     // V: [bh][S][64] (1 plane)

// ---------------- helpers ----------------
__device__ __forceinline__ uint32_t smem_u32(const void* p) {
    uint32_t a;
    asm("{ .reg .u64 t; cvta.to.shared.u64 t, %1; cvt.u32.u64 %0, t; }" : "=r"(a) : "l"(p));
    return a;
}
__device__ __forceinline__ void ldsm4(uint32_t* r, uint32_t addr) {
    asm volatile("ldmatrix.sync.aligned.m8n8.x4.shared.b16 {%0,%1,%2,%3}, [%4];"
                 : "=r"(r[0]), "=r"(r[1]), "=r"(r[2]), "=r"(r[3]) : "r"(addr));
}
__device__ __forceinline__ void ldsm4t(uint32_t* r, uint32_t addr) {
    asm volatile("ldmatrix.sync.aligned.m8n8.x4.trans.shared.b16 {%0,%1,%2,%3}, [%4];"
                 : "=r"(r[0]), "=r"(r[1]), "=r"(r[2]), "=r"(r[3]) : "r"(addr));
}
// fp16 MMA, non-volatile (pure register op; lets ptxas interleave)
__device__ __forceinline__ void mma16816(float* c, const uint32_t* a, uint32_t b0, uint32_t b1) {
    asm("mma.sync.aligned.m16n8k16.row.col.f32.f16.f16.f32 "
        "{%0,%1,%2,%3}, {%4,%5,%6,%7}, {%8,%9}, {%0,%1,%2,%3};"
        : "+f"(c[0]), "+f"(c[1]), "+f"(c[2]), "+f"(c[3])
        : "r"(a[0]), "r"(a[1]), "r"(a[2]), "r"(a[3]), "r"(b0), "r"(b1));
}
__device__ __forceinline__ void cpasync16(uint32_t dst, const void* src) {
    asm volatile("cp.async.cg.shared.global [%0], [%1], 16;" :: "r"(dst), "l"(src));
}
__device__ __forceinline__ void cp_commit() {
    asm volatile("cp.async.commit_group;" ::: "memory");
}
__device__ __forceinline__ uint32_t packhf(float a, float b) {
    __half2 h = __floats2half2_rn(a, b);
    return *(uint32_t*)&h;
}
__device__ __forceinline__ uint32_t packhlo(float a, float b, uint32_t hbits) {
    __half2 h = *(__half2*)&hbits;
    return packhf(a - __low2float(h), b - __high2float(h));
}
__device__ __forceinline__ float ex2(float x) {
    float r; asm("ex2.approx.ftz.f32 %0, %1;" : "=f"(r) : "f"(x)); return r;
}

// log2(e) folded into Q so attention uses raw ex2
#define QSCALE (0.125f * 1.4426950408889634f)

__device__ __forceinline__ uint32_t swz128(uint32_t off) {
    return off ^ ((off >> 3) & 0x70);
}

// ---------------- fp32 -> fp16 conversions ----------------
__global__ void split_act(const float* __restrict__ src, __half* __restrict__ dst)
{
    int i = blockIdx.x * blockDim.x + threadIdx.x;
    int r  = i >> 9;
    int cp = i & 511;
    float2 v = *(const float2*)(src + (size_t)r * ND + cp * 2);
    __half2 hh = __floats2half2_rn(v.x, v.y);
    __half2 ll = __floats2half2_rn(v.x - __low2float(hh), v.y - __high2float(hh));
    __half2* d2 = (__half2*)(dst + (size_t)r * KX2) + cp;
    d2[0]   = hh;
    d2[512] = ll;
}
__global__ void split_w(const float* __restrict__ Wq, const float* __restrict__ Wk,
                        const float* __restrict__ Wv, const float* __restrict__ Wo,
                        __half* __restrict__ wqkv, __half* __restrict__ wo)
{
    int which = blockIdx.y;
    const float* src = (which == 0) ? Wq : (which == 1) ? Wk : (which == 2) ? Wv : Wo;
    __half* dst = (which == 3) ? wo : wqkv + (size_t)which * ND * ND;
    int i = blockIdx.x * blockDim.x + threadIdx.x;
    int r  = i >> 9;
    int cp = i & 511;
    float2 v = *(const float2*)(src + (size_t)r * ND + cp * 2);
    ((__half2*)(dst + (size_t)r * ND))[cp] = __floats2half2_rn(v.x, v.y);
}

// ---------------- HMMA fp16 NT GEMM: C = Ah*W^T + Al*W^T (R13) --------------
static constexpr int GEMM_NT   = 1024 / 64;   // 16 stages
static constexpr int STAGE_B   = 3 * 16384;   // 49152
static constexpr int GEMM_SMEM = 2 * STAGE_B; // 98304

__device__ __forceinline__ void gemm_cp(const __half* __restrict__ A,
                                        const __half* __restrict__ Bw,
                                        int m0, int n0, int k0,
                                        uint32_t sbuf, int tid)
{
    #pragma unroll
    for (int i = 0; i < 12; i++) {
        int c = tid + i * 256;            // 0..3071 16B chunks
        int tile = c >> 10;               // 0:Ah 1:Al 2:W
        int cc = c & 1023;
        int r = cc >> 3, col16 = cc & 7;
        const __half* src = (tile < 2)
            ? A  + (size_t)(m0 + r) * KX2 + tile * 1024 + k0 + col16 * 8
            : Bw + (size_t)(n0 + r) * ND + k0 + col16 * 8;
        uint32_t off = (uint32_t)(r * 128 + col16 * 16);
        cpasync16(sbuf + tile * 16384u + swz128(off), src);
    }
}

template<int OMODE>   // 0: fp32 out [M,ND]; 1: merged QKV -> head layouts
__global__ void __launch_bounds__(256, 2)
gemm_mma(const __half* __restrict__ A, const __half* __restrict__ Bw,
         float* __restrict__ outF,
         __half* __restrict__ qp, __half* __restrict__ kp, __half* __restrict__ vp)
{
    extern __shared__ __align__(1024) char smem[];
    const int tid  = threadIdx.x;
    const int lane = tid & 31;
    const int wid  = tid >> 5;
    const int warp_m = wid & 1;    // 2 x 64 rows
    const int warp_n = wid >> 1;   // 4 x 32 cols
    const int m0 = blockIdx.y * 128;
    const int n0 = blockIdx.x * 128;

    const uint32_t sbase = smem_u32(smem);
    const int qrow = lane & 15;
    const int qcol = lane >> 4;

    float acc[4][4][4];
    #pragma unroll
    for (int a = 0; a < 4; a++)
        #pragma unroll
        for (int b = 0; b < 4; b++)
            #pragma unroll
            for (int c = 0; c < 4; c++) acc[a][b][c] = 0.f;

    gemm_cp(A, Bw, m0, n0, 0, sbase, tid); cp_commit();

    #pragma unroll 1
    for (int t = 0; t < GEMM_NT; t++) {
        asm volatile("cp.async.wait_group 0;" ::: "memory");
        __syncthreads();
        if (t + 1 < GEMM_NT) {
            gemm_cp(A, Bw, m0, n0, (t + 1) * 64,
                    sbase + (uint32_t)((t + 1) & 1) * STAGE_B, tid);
            cp_commit();
        }

        const uint32_t sAh = sbase + (uint32_t)(t & 1) * STAGE_B;
        const uint32_t sAl = sAh + 16384u;
        const uint32_t sB  = sAh + 32768u;

        #pragma unroll
        for (int ks = 0; ks < 4; ks++) {
            uint32_t ah[4][4], al[4][4];
            #pragma unroll
            for (int mi = 0; mi < 4; mi++) {
                uint32_t off = (uint32_t)((warp_m * 64 + mi * 16 + qrow) * 128
                                          + (ks * 2 + qcol) * 16);
                off = swz128(off);
                ldsm4(ah[mi], sAh + off);
                ldsm4(al[mi], sAl + off);
            }
            #pragma unroll
            for (int nj = 0; nj < 2; nj++) {
                uint32_t bh[4];
                uint32_t off = (uint32_t)((warp_n * 32 + nj * 16 + qrow) * 128
                                          + (ks * 2 + qcol) * 16);
                ldsm4(bh, sB + swz128(off));
                #pragma unroll
                for (int mi = 0; mi < 4; mi++)
                    #pragma unroll
                    for (int c2 = 0; c2 < 2; c2++) {
                        float* cc = acc[mi][nj * 2 + c2];
                        mma16816(cc, ah[mi], bh[c2], bh[2 + c2]);
                        mma16816(cc, al[mi], bh[c2], bh[2 + c2]);
                    }
            }
        }
    }

    const int tr = lane >> 2;
    const int tc = (lane & 3) * 2;
    const int which = n0 >> 10;                 // 0:Q 1:K 2:V (OMODE 1)
    const float scale = (OMODE == 1 && which == 0) ? QSCALE : 1.f;
    const int ncol0 = n0 & 1023;

    #pragma unroll
    for (int mi = 0; mi < 4; mi++) {
        #pragma unroll
        for (int ni = 0; ni < 4; ni++) {
            const int row = m0 + warp_m * 64 + mi * 16 + tr;
            const int col = (OMODE ? ncol0 : n0) + warp_n * 32 + ni * 8 + tc;
            float* cc = acc[mi][ni];
            #pragma unroll
            for (int half = 0; half < 2; half++) {
                const int r = row + half * 8;
                float2 val = half ? make_float2(cc[2], cc[3]) : make_float2(cc[0], cc[1]);
                if (OMODE == 0) {
                    *(float2*)(outF + (size_t)r * ND + col) = val;
                } else {
                    val.x *= scale; val.y *= scale;
                    const int b = r >> 11, s = r & (NS - 1);
                    const int h = col >> 6, ch = col & 63;
                    if (which == 0) {   // Q: 2 fp16 planes
                        __half2 hi = __floats2half2_rn(val.x, val.y);
                        __half2 lo = __floats2half2_rn(val.x - __low2float(hi),
                                                       val.y - __high2float(hi));
                        __half* base = qp + (((size_t)(b * NH + h) * 2) * NS + s) * 64 + ch;
                        *(__half2*)base           = hi;
                        *(__half2*)(base + NS*64) = lo;
                    } else {            // K/V: single fp16 plane
                        __half* dst = ((which == 1) ? kp : vp)
                            + ((size_t)(b * NH + h) * NS + s) * 64 + ch;
                        *(__half2*)dst = __floats2half2_rn(val.x, val.y);
                    }
                }
            }
        }
    }
}

// ---------------------------------------------------------------------------
// HMMA fp16 causal flash attention — R13 (64-row CTAs, 3 CTA/SM, 3-buffer KV
// ring, wait_group 1 deep prefetch). Grid: x=bh, y=qt (big tiles first).
// ---------------------------------------------------------------------------
static constexpr int ATTN_SMEM = 16384 + 3 * 16384;  // 65536

__global__ void __launch_bounds__(128, 3)
fattn(const __half* __restrict__ Qg, const __half* __restrict__ Kg,
      const __half* __restrict__ Vg, __half* __restrict__ As)
{
    extern __shared__ __align__(1024) char sm[];
    const uint32_t sb = smem_u32(sm);
    const int bh  = blockIdx.x;
    const int qt  = (int)gridDim.y - 1 - (int)blockIdx.y;  // big tiles first
    const int tid = threadIdx.x, lane = tid & 31, w = tid >> 5;

    const __half* Qbh = Qg + (size_t)bh * 2 * NS * 64;
    const __half* Kbh = Kg + (size_t)bh * NS * 64;
    const __half* Vbh = Vg + (size_t)bh * NS * 64;

    // Q tile: 2 planes x 64 x 64 fp16 = 16KB, SW128 swizzle (128B rows)
    #pragma unroll
    for (int i = 0; i < 8; i++) {
        int c = tid + i * 128;             // 0..1023 16B chunks
        int p = c >> 9, r = (c >> 3) & 63, col16 = c & 7;
        uint4 v = *(const uint4*)(Qbh + (size_t)p * NS * 64
                                  + (size_t)(qt * 64 + r) * 64 + col16 * 8);
        uint32_t off = (uint32_t)(r * 128 + col16 * 16);
        *(uint4*)(sm + p * 8192 + swz128(off)) = v;
    }

    const int nkt = qt + 1;

    auto load_kv = [&](int kt, int buf) {
        const int kv0 = kt * 64;
        #pragma unroll
        for (int i = 0; i < 8; i++) {
            int c = tid + i * 128;         // 0..1023
            int p = c >> 9;                // 0:K 1:V
            int r = (c >> 3) & 63, col16 = c & 7;
            const __half* src = (p == 0 ? Kbh : Vbh)
                + (size_t)(kv0 + r) * 64 + col16 * 8;
            uint32_t off = (uint32_t)(r * 128 + col16 * 16);
            cpasync16(sb + 16384 + buf * 16384 + p * 8192 + swz128(off), src);
        }
        cp_commit();
    };

    load_kv(0, 0);
    if (nkt > 1) load_kv(1, 1);

    // hoisted Q-frag addresses (kt-invariant)
    uint32_t qaddr[4];
    #pragma unroll
    for (int ks = 0; ks < 4; ks++) {
        uint32_t off = (uint32_t)((w * 16 + (lane & 15)) * 128
                                  + (ks * 2 + (lane >> 4)) * 16);
        qaddr[ks] = sb + swz128(off);
    }

    float m[2], l[2];
    m[0] = m[1] = -1e30f;
    l[0] = l[1] = 0.f;

    float o[8][4];
    #pragma unroll
    for (int b = 0; b < 8; b++)
        #pragma unroll
        for (int c = 0; c < 4; c++) o[b][c] = 0.f;

    const int qw0 = qt * 64 + w * 16;

    int buf_c = 0;
    for (int kt = 0; kt < nkt; kt++) {
        if (kt + 1 < nkt) {
            asm volatile("cp.async.wait_group 1;" ::: "memory");
        } else {
            asm volatile("cp.async.wait_group 0;" ::: "memory");
        }
        __syncthreads();   // stage kt visible; all warps done with buf(kt-1)
        if (kt + 2 < nkt) {
            int bi = buf_c + 2; if (bi >= 3) bi -= 3;
            load_kv(kt + 2, bi);     // overlaps compute(kt) and wait(kt+1)
        }

        const uint32_t sK = sb + 16384 + (uint32_t)buf_c * 16384u;
        const uint32_t sV = sK + 8192u;

        float s_[8][4];
        #pragma unroll
        for (int b = 0; b < 8; b++)
            #pragma unroll
            for (int c = 0; c < 4; c++) s_[b][c] = 0.f;

        // ---- S = (Qh + Ql) * K16 ----
        #pragma unroll
        for (int ks = 0; ks < 4; ks++) {
            uint32_t ah[4], al[4], bb[4][4];
            ldsm4(ah, qaddr[ks]);            // Q hi
            ldsm4(al, qaddr[ks] + 8192u);    // Q lo
            #pragma unroll
            for (int nj = 0; nj < 4; nj++) {
                uint32_t off = (uint32_t)((nj * 16 + (lane & 15)) * 128
                                          + (ks * 2 + (lane >> 4)) * 16);
                ldsm4(bb[nj], sK + swz128(off));
            }
            #pragma unroll
            for (int ni = 0; ni < 8; ni++)
                mma16816(s_[ni], ah, bb[ni >> 1][ni & 1], bb[ni >> 1][2 + (ni & 1)]);
            #pragma unroll
            for (int ni = 0; ni < 8; ni++)
                mma16816(s_[ni], al, bb[ni >> 1][ni & 1], bb[ni >> 1][2 + (ni & 1)]);
        }

        // ---- causal mask (only when the tile crosses this warp's rows) ----
        if (kt * 64 + 63 > qw0) {
            #pragma unroll
            for (int ni = 0; ni < 8; ni++)
                #pragma unroll
                for (int c = 0; c < 4; c++) {
                    int qr = qw0 + ((c >> 1) << 3) + (lane >> 2);
                    int kc = kt * 64 + ni * 8 + ((lane & 3) << 1) + (c & 1);
                    if (kc > qr) s_[ni][c] = -1e30f;
                }
        }

        // ---- online softmax in log2 domain ----
        #pragma unroll
        for (int rh = 0; rh < 2; rh++) {
            float mx = -1e30f;
            #pragma unroll
            for (int ni = 0; ni < 8; ni++)
                mx = fmaxf(mx, fmaxf(s_[ni][rh*2], s_[ni][rh*2+1]));
            mx = fmaxf(mx, __shfl_xor_sync(0xffffffffu, mx, 1));
            mx = fmaxf(mx, __shfl_xor_sync(0xffffffffu, mx, 2));
            float mn = fmaxf(m[rh], mx);
            float sc = ex2(m[rh] - mn);
            m[rh] = mn;
            float sum = 0.f;
            #pragma unroll
            for (int ni = 0; ni < 8; ni++) {
                float p0 = ex2(s_[ni][rh*2]   - mn);
                float p1 = ex2(s_[ni][rh*2+1] - mn);
                s_[ni][rh*2] = p0; s_[ni][rh*2+1] = p1;
                sum += p0 + p1;
            }
            sum += __shfl_xor_sync(0xffffffffu, sum, 1);
            sum += __shfl_xor_sync(0xffffffffu, sum, 2);
            l[rh] = l[rh] * sc + sum;
            #pragma unroll
            for (int ni = 0; ni < 8; ni++) {
                o[ni][rh*2]   *= sc;
                o[ni][rh*2+1] *= sc;
            }
        }

        // ---- O += (Ph + Pl) * V16 ----
        #pragma unroll
        for (int ks = 0; ks < 4; ks++) {
            uint32_t ah[4], al[4], bv[4][4];
            const float* t0 = s_[2*ks];
            const float* t1 = s_[2*ks+1];
            ah[0] = packhf(t0[0], t0[1]);
            ah[1] = packhf(t0[2], t0[3]);
            ah[2] = packhf(t1[0], t1[1]);
            ah[3] = packhf(t1[2], t1[3]);
            al[0] = packhlo(t0[0], t0[1], ah[0]);
            al[1] = packhlo(t0[2], t0[3], ah[1]);
            al[2] = packhlo(t1[0], t1[1], ah[2]);
            al[3] = packhlo(t1[2], t1[3], ah[3]);
            #pragma unroll
            for (int nj = 0; nj < 4; nj++) {
                uint32_t off = (uint32_t)((ks * 16 + (lane & 15)) * 128
                                          + (nj * 2 + (lane >> 4)) * 16);
                ldsm4t(bv[nj], sV + swz128(off));
            }
            #pragma unroll
            for (int nd = 0; nd < 8; nd++) {
                uint32_t b0 = bv[nd >> 1][(nd & 1) * 2];
                uint32_t b1 = bv[nd >> 1][(nd & 1) * 2 + 1];
                mma16816(o[nd], ah, b0, b1);
                mma16816(o[nd], al, b0, b1);
            }
        }

        buf_c = (buf_c == 2) ? 0 : buf_c + 1;
    }

    // epilogue: O/l -> 2-plane fp16 rows [hi | lo] of Wo GEMM's A operand
    const int b = bh >> 4, h = bh & 15;
    #pragma unroll
    for (int rh = 0; rh < 2; rh++) {
        float invl = 1.f / l[rh];
        int row = qw0 + rh * 8 + (lane >> 2);
        __half* rbase = As + (size_t)(b * NS + row) * KX2 + h * 64;
        #pragma unroll
        for (int ni = 0; ni < 8; ni++) {
            float vx = o[ni][rh*2] * invl;
            float vy = o[ni][rh*2+1] * invl;
            __half2 hi = __floats2half2_rn(vx, vy);
            __half2 lo = __floats2half2_rn(vx - __low2float(hi),
                                           vy - __high2float(hi));
            __half* dst = rbase + ni * 8 + ((lane & 3) << 1);
            *(__half2*)dst          = hi;
            *(__half2*)(dst + 1024) = lo;
        }
    }
}

// ---------------------------------------------------------------------------
extern "C" void kernel_launch(void* const* d_in, const int* in_sizes, int n_in,
                              void* d_out, int out_size)
{
    const float* x  = (const float*)d_in[0];
    const float* Wq = (const float*)d_in[1];
    const float* Wk = (const float*)d_in[2];
    const float* Wv = (const float*)d_in[3];
    const float* Wo = (const float*)d_in[4];
    float* out = (float*)d_out;

    __half *xs, *as, *wqkv, *wo, *q, *k, *v;
    cudaGetSymbolAddress((void**)&xs,   g_xs);
    cudaGetSymbolAddress((void**)&as,   g_as);
    cudaGetSymbolAddress((void**)&wqkv, g_wqkv);
    cudaGetSymbolAddress((void**)&wo,   g_wo);
    cudaGetSymbolAddress((void**)&q,    g_q);
    cudaGetSymbolAddress((void**)&k,    g_k);
    cudaGetSymbolAddress((void**)&v,    g_v);

    cudaFuncSetAttribute(gemm_mma<0>, cudaFuncAttributeMaxDynamicSharedMemorySize, GEMM_SMEM);
    cudaFuncSetAttribute(gemm_mma<1>, cudaFuncAttributeMaxDynamicSharedMemorySize, GEMM_SMEM);
    cudaFuncSetAttribute(fattn, cudaFuncAttributeMaxDynamicSharedMemorySize, ATTN_SMEM);

    split_act<<<MROWS * (ND/2) / 256, 256>>>(x, xs);
    split_w<<<dim3(ND * (ND/2) / 256, 4), 256>>>(Wq, Wk, Wv, Wo, wqkv, wo);

    // fused QKV projection: N = 3072
    gemm_mma<1><<<dim3(3 * ND / 128, MROWS / 128), 256, GEMM_SMEM>>>(
        xs, wqkv, nullptr, q, k, v);

    fattn<<<dim3(NB * NH, NS / 64), 128, ATTN_SMEM>>>(q, k, v, as);

    gemm_mma<0><<<dim3(ND / 128, MROWS / 128), 256, GEMM_SMEM>>>(
        as, wo, out, nullptr, nullptr, nullptr);
}